// round 16
// baseline (speedup 1.0000x reference)
#include <cuda_runtime.h>
#include <cuda_fp16.h>
#include <math.h>

// Problem constants (fixed by the dataset)
#define E_MAX   100000
#define ND_MAX  10000
#define C_DIM   128
#define MLP_IN  64
#define HID     128
#define WOUT    512      // 4 * 128
#define SH_DIM  16
#define OUT_COLS 2048    // 128 * (1+3+5+7)
#define EPB     64       // edges per block

// -------- device scratch (static allocation: allowed) --------
__device__ int g_count [ND_MAX];
__device__ int g_cursor[ND_MAX];
__device__ int g_offset[ND_MAX + 1];
__device__ int g_elist [E_MAX];
// Weights pre-scaled fp16, packed as k-pairs: word[r*N+n] = (k=2r, k=2r+1)
__device__ unsigned int g_W2p[64 * WOUT];   // [64 kpairs][512 n]
__device__ unsigned int g_W1p[32 * HID];    // [32 kpairs][128 n]

// ==================== CSR build ====================

__global__ void zero_kernel(int nd) {
    int i = blockIdx.x * blockDim.x + threadIdx.x;
    if (i < nd) { g_count[i] = 0; g_cursor[i] = 0; }
}

__global__ void hist_kernel(const int* __restrict__ dst, int E) {
    int e = blockIdx.x * blockDim.x + threadIdx.x;
    if (e < E) atomicAdd(&g_count[dst[e]], 1);
}

__global__ void scan_kernel(int nd) {
    __shared__ int s[1024];
    int t = threadIdx.x;
    int chunk = (nd + 1023) / 1024;
    int beg = t * chunk;
    int end = min(beg + chunk, nd);
    int sum = 0;
    for (int i = beg; i < end; i++) sum += g_count[i];
    s[t] = sum;
    __syncthreads();
    for (int off = 1; off < 1024; off <<= 1) {
        int v = (t >= off) ? s[t - off] : 0;
        __syncthreads();
        s[t] += v;
        __syncthreads();
    }
    int run = s[t] - sum;
    for (int i = beg; i < end; i++) {
        g_offset[i] = run;
        run += g_count[i];
    }
    if (t == 1023) g_offset[nd] = s[1023];
}

__global__ void fill_kernel(const int* __restrict__ dst, int E) {
    int e = blockIdx.x * blockDim.x + threadIdx.x;
    if (e < E) {
        int d = dst[e];
        int p = atomicAdd(&g_cursor[d], 1);
        g_elist[g_offset[d] + p] = e;
    }
}

// ==================== weight fp16 pack (W1 + W2) ====================

__global__ void pack_kernel(const float* __restrict__ W1,
                            const float* __restrict__ W2) {
    int idx = blockIdx.x * blockDim.x + threadIdx.x;
    if (idx < 64 * WOUT) {                      // W2: 1/sqrt(128)
        int r = idx >> 9, n = idx & 511;
        const float w2s = 0.08838834764831845f;
        float v0 = W2[(size_t)(2 * r)     * WOUT + n] * w2s;
        float v1 = W2[(size_t)(2 * r + 1) * WOUT + n] * w2s;
        __half2 hp = __floats2half2_rn(v0, v1);
        g_W2p[idx] = *(unsigned int*)&hp;
    }
    if (idx < 32 * HID) {                       // W1: 1/8
        int r = idx >> 7, n = idx & 127;
        float v0 = W1[(size_t)(2 * r)     * HID + n] * 0.125f;
        float v1 = W1[(size_t)(2 * r + 1) * HID + n] * 0.125f;
        __half2 hp = __floats2half2_rn(v0, v1);
        g_W1p[idx] = *(unsigned int*)&hp;
    }
}

// ==================== pre-zero rows that get atomics (or nothing) ====================
// A dst row needs zeroing iff it is empty, or its edge range crosses an
// EPB-block boundary (then >=2 blocks atomicAdd into it).

__global__ void prezero_kernel(float* __restrict__ out, int nd) {
    int d = blockIdx.x;
    if (d >= nd) return;
    int beg = g_offset[d], end = g_offset[d + 1];
    bool nz = (beg == end) || ((beg / EPB) != ((end - 1) / EPB));
    if (!nz) return;
    float4* o4 = (float4*)(out + (size_t)d * OUT_COLS);
    for (int i = threadIdx.x; i < OUT_COLS / 4; i += blockDim.x)
        o4[i] = make_float4(0.f, 0.f, 0.f, 0.f);
}

// ==================== fused MLP + tensor-product + scatter ====================
// 64 edges per block (in CSR dst-sorted order), 256 threads, 2 blocks/SM.
// Phase A: stage edge metadata + emb (fp16) + W1p.
// Phase B: H = silu(E @ W1p) via fp16 mma.
// Phase C (per 256-col chunk): MMA vs W2p -> stage fp16 in smem -> immediately
//   multiply by xsrc & sh, accumulate per-dst runs in registers, flush runs to
//   out (plain store for block-interior dst, atomicAdd for split dst).
//
// smem (bytes):
//   [0, 17408)       s_H fp16 [64][136]
//   [17408, 84992)   base2: A/B: s_E fp16[64][72] + s_W1p u32[32][136]
//                           C:  s_W2 u32[64][264] / s_ep fp16[64][264]
//   [84992, 89088)   s_sh f32 [64][16]
//   [89088, ...)     s_eid, s_src, s_d (64 ints each), s_rs[65], s_nr

#define HSTR 136
#define ESTR 72
#define WCHS 264
#define EPSTR 264
#define SMEM_BYTES 90240

__device__ __forceinline__ void mma_fp16(float* c, const unsigned* a, unsigned b0, unsigned b1) {
    asm volatile(
        "mma.sync.aligned.m16n8k16.row.col.f32.f16.f16.f32 "
        "{%0,%1,%2,%3}, {%4,%5,%6,%7}, {%8,%9}, {%0,%1,%2,%3};"
        : "+f"(c[0]), "+f"(c[1]), "+f"(c[2]), "+f"(c[3])
        : "r"(a[0]), "r"(a[1]), "r"(a[2]), "r"(a[3]), "r"(b0), "r"(b1));
}

__device__ __forceinline__ float silu_f(float v) {
    return v / (1.f + __expf(-v));
}

__global__ __launch_bounds__(256, 2)
void fused_kernel(const float* __restrict__ emb,
                  const float* __restrict__ xsrc,
                  const float* __restrict__ sh,
                  const int*   __restrict__ src,
                  const int*   __restrict__ dst,
                  float*       __restrict__ out,
                  int E) {
    extern __shared__ char sm[];
    __half* s_H  = (__half*)sm;
    char*   base2 = sm + 17408;
    float*  s_sh = (float*)(sm + 84992);
    int*    s_eid = (int*)(sm + 89088);
    int*    s_src = (int*)(sm + 89344);
    int*    s_d   = (int*)(sm + 89600);
    int*    s_rs  = (int*)(sm + 89856);   // [65]
    int*    s_nr  = (int*)(sm + 90120);

    int tid  = threadIdx.x;
    int lane = tid & 31;
    int w    = tid >> 5;
    int q    = lane >> 2;
    int tg   = lane & 3;
    int blockBeg = blockIdx.x * EPB;
    int cnt = min(EPB, E - blockBeg);

    // ---------- phase A: metadata + emb + W1p ----------
    if (tid < cnt) s_eid[tid] = g_elist[blockBeg + tid];
    __syncthreads();
    if (tid < cnt) {
        int e = s_eid[tid];
        s_src[tid] = src[e];
        s_d[tid]   = dst[e];
    }
    for (int i = tid; i < cnt * SH_DIM; i += 256)
        s_sh[i] = sh[(size_t)s_eid[i >> 4] * SH_DIM + (i & 15)];

    __half*   s_E   = (__half*)base2;                 // [64][ESTR]
    unsigned* s_W1p = (unsigned*)(base2 + 9216);      // [32][136]
    for (int i = tid; i < EPB * MLP_IN; i += 256) {
        int e = i >> 6, k = i & 63;
        float v = (e < cnt) ? emb[(size_t)s_eid[e] * MLP_IN + k] : 0.f;
        s_E[e * ESTR + k] = __float2half_rn(v);
    }
    for (int i = tid; i < 32 * 32; i += 256) {
        int r = i >> 5, n4 = i & 31;
        ((uint4*)(s_W1p + r * 136))[n4] = ((const uint4*)g_W1p)[r * 32 + n4];
    }
    __syncthreads();

    // run compaction (thread 0) — overlaps other warps' phase B
    if (tid == 0) {
        int nr = 0;
        for (int i = 0; i < cnt; i++)
            if (i == 0 || s_d[i] != s_d[i - 1]) s_rs[nr++] = i;
        s_rs[nr] = cnt;
        *s_nr = nr;
    }

    // ---------- phase B: H = silu(E @ W1p) ----------
    {
        const unsigned* E32 = (const unsigned*)s_E;   // row stride 36 u32
        int mt = w & 3;
        int nh = w >> 2;

        float hacc[8][4];
#pragma unroll
        for (int nt = 0; nt < 8; nt++)
#pragma unroll
            for (int r = 0; r < 4; r++) hacc[nt][r] = 0.f;

#pragma unroll
        for (int kt = 0; kt < 4; kt++) {
            unsigned a[4];
            int i0 = (mt * 16 + q) * 36 + kt * 8 + tg;
            a[0] = E32[i0];
            a[1] = E32[i0 + 8 * 36];
            a[2] = E32[i0 + 4];
            a[3] = E32[i0 + 8 * 36 + 4];
            int r0 = kt * 8 + tg;
#pragma unroll
            for (int nt = 0; nt < 8; nt++) {
                int ncol = nh * 64 + nt * 8 + q;
                unsigned b0 = s_W1p[r0 * 136 + ncol];
                unsigned b1 = s_W1p[(r0 + 4) * 136 + ncol];
                mma_fp16(hacc[nt], a, b0, b1);
            }
        }
#pragma unroll
        for (int nt = 0; nt < 8; nt++) {
            int col = nh * 64 + nt * 8 + tg * 2;
            int row = (w & 3) * 16 + q;
            __half2 h01 = __floats2half2_rn(silu_f(hacc[nt][0]), silu_f(hacc[nt][1]));
            __half2 h23 = __floats2half2_rn(silu_f(hacc[nt][2]), silu_f(hacc[nt][3]));
            *(__half2*)&s_H[row * HSTR + col]       = h01;
            *(__half2*)&s_H[(row + 8) * HSTR + col] = h23;
        }
    }
    __syncthreads();    // s_H ready, compaction done, phase-A buffers free

    // ---------- phase C: 2 chunks of 256 cols: MMA -> stage -> scatter ----------
    unsigned* s_W2 = (unsigned*)base2;              // [64][WCHS]
    __half*   s_ep = (__half*)base2;                // staging [64][EPSTR]
    const unsigned* H32 = (const unsigned*)s_H;

    int c    = tid & 127;   // channel
    int half = tid >> 7;    // 0: first 128 chunk-cols, 1: second

    for (int nb = 0; nb < 2; nb++) {
        // load W2 chunk
        {
            const uint4* gp = ((const uint4*)g_W2p) + nb * 64;
            for (int i = tid; i < 64 * 64; i += 256) {
                int r = i >> 6, n4 = i & 63;
                ((uint4*)(s_W2 + r * WCHS))[n4] = gp[r * 128 + n4];
            }
        }
        __syncthreads();

        float acc[4][4][4];
#pragma unroll
        for (int mt = 0; mt < 4; mt++)
#pragma unroll
            for (int nt = 0; nt < 4; nt++)
#pragma unroll
                for (int r = 0; r < 4; r++) acc[mt][nt][r] = 0.f;

#pragma unroll
        for (int kt = 0; kt < 8; kt++) {
            unsigned a[4][4];
#pragma unroll
            for (int mt = 0; mt < 4; mt++) {
                int i0 = (mt * 16 + q) * (HSTR / 2) + kt * 8 + tg;
                a[mt][0] = H32[i0];
                a[mt][1] = H32[i0 + 8 * 68];
                a[mt][2] = H32[i0 + 4];
                a[mt][3] = H32[i0 + 8 * 68 + 4];
            }
            int r0 = kt * 8 + tg;
            unsigned b[4][2];
#pragma unroll
            for (int nt = 0; nt < 4; nt++) {
                int ncol = w * 32 + nt * 8 + q;
                b[nt][0] = s_W2[r0 * WCHS + ncol];
                b[nt][1] = s_W2[(r0 + 4) * WCHS + ncol];
            }
#pragma unroll
            for (int mt = 0; mt < 4; mt++)
#pragma unroll
                for (int nt = 0; nt < 4; nt++)
                    mma_fp16(acc[mt][nt], a[mt], b[nt][0], b[nt][1]);
        }

        __syncthreads();    // done reading s_W2 -> reuse region as s_ep
#pragma unroll
        for (int nt = 0; nt < 4; nt++) {
            int col = w * 32 + nt * 8 + tg * 2;
#pragma unroll
            for (int mt = 0; mt < 4; mt++) {
                int row = mt * 16 + q;
                __half2 h01 = __floats2half2_rn(acc[mt][nt][0], acc[mt][nt][1]);
                __half2 h23 = __floats2half2_rn(acc[mt][nt][2], acc[mt][nt][3]);
                *(__half2*)&s_ep[row * EPSTR + col]       = h01;
                *(__half2*)&s_ep[(row + 8) * EPSTR + col] = h23;
            }
        }
        __syncthreads();    // s_ep ready

        // ---- scatter-accumulate: per-dst runs, register accumulators ----
        // chunk nb covers l = 2nb + half; out layout per l:
        //   l=0: [0,128) 1/ch; l=1: [128,512) 3/ch; l=2: [512,1152) 5/ch; l=3: [1152,2048) 7/ch
        int l = 2 * nb + half;
        int na   = 2 * l + 1;
        int obase = (l == 0) ? c : (l == 1) ? 128 + c * 3 : (l == 2) ? 512 + c * 5 : 1152 + c * 7;
        int shoff = l * l;    // 0,1,4,9

        int nr = *s_nr;
        for (int r = 0; r < nr; r++) {
            int rs = s_rs[r], re = s_rs[r + 1];
            int d  = s_d[rs];
            float a[7];
#pragma unroll
            for (int m = 0; m < 7; m++) a[m] = 0.f;

            for (int e = rs; e < re; e++) {
                float xs = xsrc[(size_t)s_src[e] * C_DIM + c];
                float t  = __half2float(s_ep[e * EPSTR + half * 128 + c]) * xs;
                const float* sv = &s_sh[e * SH_DIM + shoff];
#pragma unroll
                for (int m = 0; m < 7; m++)
                    if (m < na) a[m] += t * sv[m];
            }

            bool atom = (r == 0      && g_offset[d]     < blockBeg) ||
                        (r == nr - 1 && g_offset[d + 1] > blockBeg + cnt);
            float* op = out + (size_t)d * OUT_COLS + obase;
            if (atom) {
#pragma unroll
                for (int m = 0; m < 7; m++)
                    if (m < na) atomicAdd(op + m, a[m]);
            } else {
#pragma unroll
                for (int m = 0; m < 7; m++)
                    if (m < na) op[m] = a[m];
            }
        }
        __syncthreads();    // epilogue done before next chunk overwrites s_ep
    }
}

// ==================== launch ====================

extern "C" void kernel_launch(void* const* d_in, const int* in_sizes, int n_in,
                              void* d_out, int out_size) {
    const float* xsrc = (const float*)d_in[0];
    const float* sh   = (const float*)d_in[1];
    const float* emb  = (const float*)d_in[2];
    const float* W1   = (const float*)d_in[3];
    const float* W2   = (const float*)d_in[4];
    const int*   src  = (const int*)d_in[5];
    const int*   dst  = (const int*)d_in[6];

    int E  = in_sizes[5];
    int nd = out_size / OUT_COLS;

    zero_kernel<<<(nd + 255) / 256, 256>>>(nd);
    hist_kernel<<<(E + 255) / 256, 256>>>(dst, E);
    scan_kernel<<<1, 1024>>>(nd);
    fill_kernel<<<(E + 255) / 256, 256>>>(dst, E);
    pack_kernel<<<(64 * WOUT + 255) / 256, 256>>>(W1, W2);
    prezero_kernel<<<nd, 128>>>((float*)d_out, nd);

    cudaFuncSetAttribute(fused_kernel, cudaFuncAttributeMaxDynamicSharedMemorySize, SMEM_BYTES);
    fused_kernel<<<(E + EPB - 1) / EPB, 256, SMEM_BYTES>>>(
        emb, xsrc, sh, src, dst, (float*)d_out, E);
}

// round 17
// speedup vs baseline: 1.2642x; 1.2642x over previous
#include <cuda_runtime.h>
#include <cuda_fp16.h>
#include <math.h>

// Problem constants (fixed by the dataset)
#define E_MAX   100000
#define ND_MAX  10000
#define C_DIM   128
#define MLP_IN  64
#define HID     128
#define WOUT    512      // 4 * 128
#define SH_DIM  16
#define OUT_COLS 2048    // 128 * (1+3+5+7)

// -------- device scratch (static allocation: allowed) --------
__device__ int    g_count [ND_MAX];
__device__ int    g_cursor[ND_MAX];
__device__ int    g_offset[ND_MAX + 1];
__device__ int    g_elist [E_MAX];
__device__ __half g_tpwh  [(size_t)E_MAX * WOUT];   // 102.4 MB edge MLP output (fp16)
// Weights pre-scaled fp16, packed as k-pairs: word[r*N+n] = (k=2r, k=2r+1)
__device__ unsigned int g_W2p[64 * WOUT];   // [64 kpairs][512 n]
__device__ unsigned int g_W1p[32 * HID];    // [32 kpairs][128 n]

// ==================== CSR build ====================

__global__ void hist_kernel(const int* __restrict__ dst, int E) {
    int e = blockIdx.x * blockDim.x + threadIdx.x;
    if (e < E) atomicAdd(&g_count[dst[e]], 1);
}

__global__ void scan_kernel(int nd) {
    __shared__ int s[1024];
    int t = threadIdx.x;
    int chunk = (nd + 1023) / 1024;
    int beg = t * chunk;
    int end = min(beg + chunk, nd);
    int sum = 0;
    for (int i = beg; i < end; i++) sum += g_count[i];
    s[t] = sum;
    __syncthreads();
    for (int off = 1; off < 1024; off <<= 1) {
        int v = (t >= off) ? s[t - off] : 0;
        __syncthreads();
        s[t] += v;
        __syncthreads();
    }
    int run = s[t] - sum;
    for (int i = beg; i < end; i++) {
        g_offset[i] = run;
        run += g_count[i];
    }
    if (t == 1023) g_offset[nd] = s[1023];
}

__global__ void fill_kernel(const int* __restrict__ dst, int E) {
    int e = blockIdx.x * blockDim.x + threadIdx.x;
    if (e < E) {
        int d = dst[e];
        int p = atomicAdd(&g_cursor[d], 1);
        g_elist[g_offset[d] + p] = e;
    }
}

// ============ merged: counter zeroing + weight fp16 pack (W1 + W2) ============

__global__ void pack_zero_kernel(const float* __restrict__ W1,
                                 const float* __restrict__ W2, int nd) {
    int idx = blockIdx.x * blockDim.x + threadIdx.x;
    if (idx < nd) { g_count[idx] = 0; g_cursor[idx] = 0; }
    if (idx < 64 * WOUT) {                      // W2: 1/sqrt(128)
        int r = idx >> 9, n = idx & 511;
        const float w2s = 0.08838834764831845f;
        float v0 = W2[(size_t)(2 * r)     * WOUT + n] * w2s;
        float v1 = W2[(size_t)(2 * r + 1) * WOUT + n] * w2s;
        __half2 hp = __floats2half2_rn(v0, v1);
        g_W2p[idx] = *(unsigned int*)&hp;
    }
    if (idx < 32 * HID) {                       // W1: 1/8
        int r = idx >> 7, n = idx & 127;
        float v0 = W1[(size_t)(2 * r)     * HID + n] * 0.125f;
        float v1 = W1[(size_t)(2 * r + 1) * HID + n] * 0.125f;
        __half2 hp = __floats2half2_rn(v0, v1);
        g_W1p[idx] = *(unsigned int*)&hp;
    }
}

// ==================== fused edge MLP (all-fp16 tensor cores) ====================
// 64 edges per block, 256 threads (8 warps), 2 blocks/SM.  (Round-11 proven.)

#define EPB 64
#define HSTR 136
#define ESTR 72
#define WCHS 264
#define EPSTR 264
#define SMEM_BYTES (17408 + 64 * WCHS * 4)   // 84992

__device__ __forceinline__ void mma_fp16(float* c, const unsigned* a, unsigned b0, unsigned b1) {
    asm volatile(
        "mma.sync.aligned.m16n8k16.row.col.f32.f16.f16.f32 "
        "{%0,%1,%2,%3}, {%4,%5,%6,%7}, {%8,%9}, {%0,%1,%2,%3};"
        : "+f"(c[0]), "+f"(c[1]), "+f"(c[2]), "+f"(c[3])
        : "r"(a[0]), "r"(a[1]), "r"(a[2]), "r"(a[3]), "r"(b0), "r"(b1));
}

__device__ __forceinline__ float silu_f(float v) {
    return v / (1.f + __expf(-v));
}

__global__ __launch_bounds__(256, 2)
void mlp_kernel(const float* __restrict__ emb, int E) {
    extern __shared__ char smraw[];
    __half* s_H = (__half*)smraw;
    char* base2 = smraw + 17408;

    int tid  = threadIdx.x;
    int lane = tid & 31;
    int w    = tid >> 5;
    int e0   = blockIdx.x * EPB;
    int q    = lane >> 2;
    int tg   = lane & 3;

    // ---------- phase A: emb -> fp16 smem, W1p -> smem ----------
    {
        __half*   s_E   = (__half*)base2;                 // [64][ESTR]
        unsigned* s_W1p = (unsigned*)(base2 + 9216);      // [32][136]
        for (int i = tid; i < EPB * MLP_IN; i += 256) {
            int e = i >> 6, k = i & 63;
            int ge = e0 + e;
            float v = (ge < E) ? emb[(size_t)ge * MLP_IN + k] : 0.f;
            s_E[e * ESTR + k] = __float2half_rn(v);
        }
        for (int i = tid; i < 32 * 32; i += 256) {
            int r = i >> 5, n4 = i & 31;
            ((uint4*)(s_W1p + r * 136))[n4] = ((const uint4*)g_W1p)[r * 32 + n4];
        }
        __syncthreads();

        // ---------- phase B: H = silu(E @ W1p) ----------
        const unsigned* E32 = (const unsigned*)s_E;       // row stride 36 u32
        int mt = w & 3;
        int nh = w >> 2;

        float hacc[8][4];
#pragma unroll
        for (int nt = 0; nt < 8; nt++)
#pragma unroll
            for (int r = 0; r < 4; r++) hacc[nt][r] = 0.f;

#pragma unroll
        for (int kt = 0; kt < 4; kt++) {
            unsigned a[4];
            int i0 = (mt * 16 + q) * 36 + kt * 8 + tg;
            a[0] = E32[i0];
            a[1] = E32[i0 + 8 * 36];
            a[2] = E32[i0 + 4];
            a[3] = E32[i0 + 8 * 36 + 4];
            int r0 = kt * 8 + tg;
#pragma unroll
            for (int nt = 0; nt < 8; nt++) {
                int ncol = nh * 64 + nt * 8 + q;
                unsigned b0 = s_W1p[r0 * 136 + ncol];
                unsigned b1 = s_W1p[(r0 + 4) * 136 + ncol];
                mma_fp16(hacc[nt], a, b0, b1);
            }
        }
#pragma unroll
        for (int nt = 0; nt < 8; nt++) {
            int col = nh * 64 + nt * 8 + tg * 2;
            int row = mt * 16 + q;
            __half2 h01 = __floats2half2_rn(silu_f(hacc[nt][0]), silu_f(hacc[nt][1]));
            __half2 h23 = __floats2half2_rn(silu_f(hacc[nt][2]), silu_f(hacc[nt][3]));
            *(__half2*)&s_H[row * HSTR + col]       = h01;
            *(__half2*)&s_H[(row + 8) * HSTR + col] = h23;
        }
    }

    // ---------- phase C: TPW = H @ W2p, 2 chunks of 256 n-cols ----------
    unsigned* s_W2 = (unsigned*)base2;              // [64][WCHS]
    __half*   s_ep = (__half*)base2;                // epilogue staging [64][EPSTR]
    const unsigned* H32 = (const unsigned*)s_H;

    for (int nb = 0; nb < 2; nb++) {
        __syncthreads();
        {
            const uint4* gp = ((const uint4*)g_W2p) + nb * 64;
            for (int i = tid; i < 64 * 64; i += 256) {
                int r = i >> 6, n4 = i & 63;
                ((uint4*)(s_W2 + r * WCHS))[n4] = gp[r * 128 + n4];
            }
        }
        __syncthreads();

        float acc[4][4][4];
#pragma unroll
        for (int mt = 0; mt < 4; mt++)
#pragma unroll
            for (int nt = 0; nt < 4; nt++)
#pragma unroll
                for (int r = 0; r < 4; r++) acc[mt][nt][r] = 0.f;

#pragma unroll
        for (int kt = 0; kt < 8; kt++) {
            unsigned a[4][4];
#pragma unroll
            for (int mt = 0; mt < 4; mt++) {
                int i0 = (mt * 16 + q) * (HSTR / 2) + kt * 8 + tg;
                a[mt][0] = H32[i0];
                a[mt][1] = H32[i0 + 8 * 68];
                a[mt][2] = H32[i0 + 4];
                a[mt][3] = H32[i0 + 8 * 68 + 4];
            }
            int r0 = kt * 8 + tg;
            unsigned b[4][2];
#pragma unroll
            for (int nt = 0; nt < 4; nt++) {
                int ncol = w * 32 + nt * 8 + q;
                b[nt][0] = s_W2[r0 * WCHS + ncol];
                b[nt][1] = s_W2[(r0 + 4) * WCHS + ncol];
            }
#pragma unroll
            for (int mt = 0; mt < 4; mt++)
#pragma unroll
                for (int nt = 0; nt < 4; nt++)
                    mma_fp16(acc[mt][nt], a[mt], b[nt][0], b[nt][1]);
        }

        __syncthreads();    // done reading s_W2 -> reuse as staging
#pragma unroll
        for (int nt = 0; nt < 4; nt++) {
            int col = w * 32 + nt * 8 + tg * 2;
#pragma unroll
            for (int mt = 0; mt < 4; mt++) {
                int row = mt * 16 + q;
                __half2 h01 = __floats2half2_rn(acc[mt][nt][0], acc[mt][nt][1]);
                __half2 h23 = __floats2half2_rn(acc[mt][nt][2], acc[mt][nt][3]);
                *(__half2*)&s_ep[row * EPSTR + col]       = h01;
                *(__half2*)&s_ep[(row + 8) * EPSTR + col] = h23;
            }
        }
        __syncthreads();
        // coalesced copy-out: 64 rows x 32 uint4
        for (int i = tid; i < 64 * 32; i += 256) {
            int r = i >> 5, n4 = i & 31;
            int row = e0 + r;
            if (row < E) {
                uint4 v = *(const uint4*)((const char*)s_ep + r * (EPSTR * 2) + n4 * 16);
                *(uint4*)&g_tpwh[(size_t)row * WOUT + nb * 256 + n4 * 8] = v;
            }
        }
    }
}

// ==================== per-dst gather (channel-pair + edge-parity ILP) ====================
// Block = one dst node, 128 threads. Thread owns channel pair (2*c2, 2*c2+1)
// and edge parity group g: vector loads (float2 xsrc, half2 tpwh) halve the
// load count; the 2-way edge split doubles per-block memory parallelism.

__global__ __launch_bounds__(128)
void gather_kernel(const float* __restrict__ xsrc,
                   const float* __restrict__ sh,
                   const int*   __restrict__ src,
                   float*       __restrict__ out) {
    int d   = blockIdx.x;
    int tid = threadIdx.x;
    int c2  = tid & 63;    // channel pair index: channels 2c2, 2c2+1
    int g   = tid >> 6;    // edge parity group 0/1
    __shared__ int   s_e[32];
    __shared__ int   s_s[32];
    __shared__ float s_shv[32 * SH_DIM];
    __shared__ float s_out[OUT_COLS];

    float acc[2][16];
#pragma unroll
    for (int k = 0; k < 2; k++)
#pragma unroll
        for (int i = 0; i < 16; i++) acc[k][i] = 0.f;

    int beg = g_offset[d], end = g_offset[d + 1];

    for (int base = beg; base < end; base += 32) {
        int cnt = min(32, end - base);
        __syncthreads();
        if (tid < cnt) s_e[tid] = g_elist[base + tid];
        __syncthreads();
        if (tid < cnt) s_s[tid] = src[s_e[tid]];
        for (int idx = tid; idx < cnt * SH_DIM; idx += 128)
            s_shv[idx] = sh[(size_t)s_e[idx >> 4] * SH_DIM + (idx & 15)];
        __syncthreads();

#pragma unroll 2
        for (int j = g; j < cnt; j += 2) {
            int e = s_e[j];
            int s = s_s[j];
            float2 xs = *(const float2*)&xsrc[(size_t)s * C_DIM + 2 * c2];
            const __half2* tp2 = (const __half2*)&g_tpwh[(size_t)e * WOUT];
            float2 t0 = __half22float2(tp2[c2]);
            float2 t1 = __half22float2(tp2[64 + c2]);
            float2 t2 = __half22float2(tp2[128 + c2]);
            float2 t3 = __half22float2(tp2[192 + c2]);
            t0.x *= xs.x; t0.y *= xs.y;
            t1.x *= xs.x; t1.y *= xs.y;
            t2.x *= xs.x; t2.y *= xs.y;
            t3.x *= xs.x; t3.y *= xs.y;
            const float* sv = &s_shv[j * SH_DIM];
            acc[0][0] += t0.x * sv[0];
            acc[1][0] += t0.y * sv[0];
#pragma unroll
            for (int m = 0; m < 3; m++) {
                acc[0][1 + m] += t1.x * sv[1 + m];
                acc[1][1 + m] += t1.y * sv[1 + m];
            }
#pragma unroll
            for (int m = 0; m < 5; m++) {
                acc[0][4 + m] += t2.x * sv[4 + m];
                acc[1][4 + m] += t2.y * sv[4 + m];
            }
#pragma unroll
            for (int m = 0; m < 7; m++) {
                acc[0][9 + m] += t3.x * sv[9 + m];
                acc[1][9 + m] += t3.y * sv[9 + m];
            }
        }
    }

    // combine the two parity groups in smem (group 0 stores, group 1 adds)
    __syncthreads();
    if (g == 0) {
#pragma unroll
        for (int k = 0; k < 2; k++) {
            int c = 2 * c2 + k;
            s_out[c] = acc[k][0];
#pragma unroll
            for (int m = 0; m < 3; m++) s_out[128  + c * 3 + m] = acc[k][1 + m];
#pragma unroll
            for (int m = 0; m < 5; m++) s_out[512  + c * 5 + m] = acc[k][4 + m];
#pragma unroll
            for (int m = 0; m < 7; m++) s_out[1152 + c * 7 + m] = acc[k][9 + m];
        }
    }
    __syncthreads();
    if (g == 1) {
#pragma unroll
        for (int k = 0; k < 2; k++) {
            int c = 2 * c2 + k;
            s_out[c] += acc[k][0];
#pragma unroll
            for (int m = 0; m < 3; m++) s_out[128  + c * 3 + m] += acc[k][1 + m];
#pragma unroll
            for (int m = 0; m < 5; m++) s_out[512  + c * 5 + m] += acc[k][4 + m];
#pragma unroll
            for (int m = 0; m < 7; m++) s_out[1152 + c * 7 + m] += acc[k][9 + m];
        }
    }
    __syncthreads();

    float4* o4 = (float4*)(out + (size_t)d * OUT_COLS);
    const float4* s4 = (const float4*)s_out;
    for (int i = tid; i < OUT_COLS / 4; i += 128) o4[i] = s4[i];
}

// ==================== launch ====================

extern "C" void kernel_launch(void* const* d_in, const int* in_sizes, int n_in,
                              void* d_out, int out_size) {
    const float* xsrc = (const float*)d_in[0];
    const float* sh   = (const float*)d_in[1];
    const float* emb  = (const float*)d_in[2];
    const float* W1   = (const float*)d_in[3];
    const float* W2   = (const float*)d_in[4];
    const int*   src  = (const int*)d_in[5];
    const int*   dst  = (const int*)d_in[6];

    int E  = in_sizes[5];
    int nd = out_size / OUT_COLS;

    pack_zero_kernel<<<(64 * WOUT + 255) / 256, 256>>>(W1, W2, nd);
    hist_kernel<<<(E + 255) / 256, 256>>>(dst, E);
    scan_kernel<<<1, 1024>>>(nd);
    fill_kernel<<<(E + 255) / 256, 256>>>(dst, E);

    cudaFuncSetAttribute(mlp_kernel, cudaFuncAttributeMaxDynamicSharedMemorySize, SMEM_BYTES);
    mlp_kernel<<<(E + EPB - 1) / EPB, 256, SMEM_BYTES>>>(emb, E);

    gather_kernel<<<nd, 128>>>(xsrc, sh, src, (float*)d_out);
}